// round 3
// baseline (speedup 1.0000x reference)
#include <cuda_runtime.h>
#include <cuda_bf16.h>
#include <stdint.h>

// Problem: output[b, :] = full_input[b, idx[b]*64 : (idx[b]+1)*64]
// B = 262144, OUTPUT_DIM = 64, NB_CTRL_SIG = 16 (row stride 1024 floats).
// Pure gather: 64 MiB read + 64 MiB write + 1 MiB idx. HBM-bound.

#define OUTPUT_DIM 64
#define ROW_STRIDE 1024        // OUTPUT_DIM * NB_CTRL_SIG
#define THREADS_PER_ROW 16     // 16 x float4 = 64 floats
#define ROWS_PER_BLOCK 16      // 256 threads / 16

__global__ __launch_bounds__(256) void mux_gather_kernel(
    const float* __restrict__ full_input,
    const int*   __restrict__ indices,
    float*       __restrict__ out,
    int batch)
{
    int tid  = blockIdx.x * blockDim.x + threadIdx.x;
    int row  = tid / THREADS_PER_ROW;
    int lane = tid % THREADS_PER_ROW;
    if (row >= batch) return;

    int idx = indices[row];  // broadcast across the 16 lanes of this row (L1/L2 hit)

    // 256-byte-aligned source block; float4 load/store, fully coalesced.
    const float4* src = reinterpret_cast<const float4*>(
        full_input + (size_t)row * ROW_STRIDE + idx * OUTPUT_DIM);
    float4* dst = reinterpret_cast<float4*>(out + (size_t)row * OUTPUT_DIM);

    dst[lane] = src[lane];
}

extern "C" void kernel_launch(void* const* d_in, const int* in_sizes, int n_in,
                              void* d_out, int out_size)
{
    const float* full_input = (const float*)d_in[0];
    const int*   indices    = (const int*)d_in[1];
    float*       out        = (float*)d_out;

    int batch = in_sizes[0] / ROW_STRIDE;  // 262144

    int threads = 256;
    int rows_per_block = threads / THREADS_PER_ROW;
    int blocks = (batch + rows_per_block - 1) / rows_per_block;

    mux_gather_kernel<<<blocks, threads>>>(full_input, indices, out, batch);
}

// round 4
// speedup vs baseline: 1.2197x; 1.2197x over previous
#include <cuda_runtime.h>
#include <cuda_bf16.h>
#include <stdint.h>

// output[b, :] = full_input[b, idx[b]*64 : (idx[b]+1)*64]
// B = 262144, OUTPUT_DIM = 64, row stride 1024 floats.
// HBM-bound gather: 64 MiB read + 64 MiB write. R3: ILP=4 rows/thread to
// raise memory-level parallelism (was 1 dependent load chain per thread).

#define OUTPUT_DIM 64
#define ROW_STRIDE 1024        // OUTPUT_DIM * NB_CTRL_SIG
#define THREADS_PER_ROW 16     // 16 x float4 = 64 floats = 256 B
#define ILP 4                  // rows per thread
#define BLOCK_THREADS 256
#define ROWS_PER_BLOCK ((BLOCK_THREADS / THREADS_PER_ROW) * ILP)  // 64

__global__ __launch_bounds__(BLOCK_THREADS) void mux_gather_ilp4(
    const float* __restrict__ full_input,
    const int*   __restrict__ indices,
    float*       __restrict__ out,
    int batch)
{
    const int lane = threadIdx.x % THREADS_PER_ROW;          // 0..15
    const int grp  = threadIdx.x / THREADS_PER_ROW;          // 0..15
    const int r0   = blockIdx.x * ROWS_PER_BLOCK + grp;      // first of 4 rows

    // Phase 1: all index loads issued back-to-back (independent, overlap latency)
    int idx[ILP];
    #pragma unroll
    for (int i = 0; i < ILP; i++) {
        int r = r0 + i * (BLOCK_THREADS / THREADS_PER_ROW);
        idx[i] = (r < batch) ? __ldg(&indices[r]) : 0;
    }

    // Phase 2: all data loads issued back-to-back (MLP = 4)
    float4 v[ILP];
    #pragma unroll
    for (int i = 0; i < ILP; i++) {
        int r = r0 + i * (BLOCK_THREADS / THREADS_PER_ROW);
        if (r < batch) {
            const float4* src = reinterpret_cast<const float4*>(
                full_input + (size_t)r * ROW_STRIDE + idx[i] * OUTPUT_DIM);
            v[i] = src[lane];
        }
    }

    // Phase 3: stores (coalesced 256 B per half-group)
    #pragma unroll
    for (int i = 0; i < ILP; i++) {
        int r = r0 + i * (BLOCK_THREADS / THREADS_PER_ROW);
        if (r < batch) {
            float4* dst = reinterpret_cast<float4*>(out + (size_t)r * OUTPUT_DIM);
            dst[lane] = v[i];
        }
    }
}

extern "C" void kernel_launch(void* const* d_in, const int* in_sizes, int n_in,
                              void* d_out, int out_size)
{
    const float* full_input = (const float*)d_in[0];
    const int*   indices    = (const int*)d_in[1];
    float*       out        = (float*)d_out;

    int batch  = in_sizes[0] / ROW_STRIDE;  // 262144
    int blocks = (batch + ROWS_PER_BLOCK - 1) / ROWS_PER_BLOCK;  // 4096

    mux_gather_ilp4<<<blocks, BLOCK_THREADS>>>(full_input, indices, out, batch);
}